// round 6
// baseline (speedup 1.0000x reference)
#include <cuda_runtime.h>
#include <cstdint>
#include <math.h>

#define TT 4096
#define DD 896

constexpr int BM = 128, BN = 128, BK = 32;
constexpr int NBLK = TT / 128;                 // 32
constexpr int NPAIR = NBLK * (NBLK + 1) / 2;   // 528 causal 128x128 blocks
constexpr int NKT_FULL = DD / BK;              // 28

// packed-stage geometry (padded strides, bank-conflict-free staging)
constexpr int A_GRP = 132;                 // words per (mtile,ks) group
constexpr int B_GRP = 68;
constexpr int A_WORDS = 32 * A_GRP;        // 8 mtiles * 4 ks = 32 groups -> 4224
constexpr int B_WORDS = 64 * B_GRP;        // 16 ntiles * 4 ks = 64 groups -> 4352
constexpr int STAGE3 = 2 * A_WORDS + 2 * B_WORDS;  // 17152 words (hi+lo A,B)
constexpr int STAGE1 = A_WORDS + B_WORDS;          // 8576 words (hi only)
constexpr unsigned DSMEM3 = 2u * STAGE3 * 4u;      // 137216 B
constexpr unsigned DSMEM1 = 2u * STAGE1 * 4u;      // 68608 B

// ---------------- scratch (device globals: allocation-free) ----------------
__device__ float g_h[(size_t)TT * DD];
__device__ float g_g[(size_t)TT * DD];
__device__ float g_sim[(size_t)TT * TT];
__device__ float g_hn2[TT];
__device__ float g_maxQ[TT];
__device__ float g_invden[TT];

// ---------------- small helpers ----------------
__device__ __forceinline__ unsigned f2tf(float f) {
    unsigned u;
    asm("cvt.rna.tf32.f32 %0, %1;" : "=r"(u) : "f"(f));
    return u;
}
__device__ __forceinline__ void tfsplit(float f, unsigned& hi, unsigned& lo) {
    hi = f2tf(f);
    lo = f2tf(f - __uint_as_float(hi));
}
__device__ __forceinline__ void mma8(float* d, const unsigned* a, const unsigned* b) {
    asm volatile(
        "mma.sync.aligned.m16n8k8.row.col.f32.tf32.tf32.f32 "
        "{%0,%1,%2,%3}, {%4,%5,%6,%7}, {%8,%9}, {%0,%1,%2,%3};\n"
        : "+f"(d[0]), "+f"(d[1]), "+f"(d[2]), "+f"(d[3])
        : "r"(a[0]), "r"(a[1]), "r"(a[2]), "r"(a[3]),
          "r"(b[0]), "r"(b[1]));
}
__device__ __forceinline__ float blockReduceSum(float v, float* sh) {
    int lane = threadIdx.x & 31, w = threadIdx.x >> 5;
#pragma unroll
    for (int o = 16; o; o >>= 1) v += __shfl_xor_sync(0xffffffffu, v, o);
    __syncthreads();
    if (lane == 0) sh[w] = v;
    __syncthreads();
    if (threadIdx.x == 0) {
        float s = 0.f;
        int nw = (blockDim.x + 31) >> 5;
        for (int i = 0; i < nw; i++) s += sh[i];
        sh[0] = s;
    }
    __syncthreads();
    return sh[0];
}
__device__ __forceinline__ float blockReduceMax(float v, float* sh) {
    int lane = threadIdx.x & 31, w = threadIdx.x >> 5;
#pragma unroll
    for (int o = 16; o; o >>= 1) v = fmaxf(v, __shfl_xor_sync(0xffffffffu, v, o));
    __syncthreads();
    if (lane == 0) sh[w] = v;
    __syncthreads();
    if (threadIdx.x == 0) {
        float m = -3.0e38f;
        int nw = (blockDim.x + 31) >> 5;
        for (int i = 0; i < nw; i++) m = fmaxf(m, sh[i]);
        sh[0] = m;
    }
    __syncthreads();
    return sh[0];
}
__device__ __forceinline__ void atomicMaxF(float* addr, float val) {
    int old = __float_as_int(*addr);
    while (__int_as_float(old) < val) {
        int assumed = old;
        old = atomicCAS((int*)addr, assumed, __float_as_int(val));
        if (old == assumed) break;
    }
}
__device__ __forceinline__ void triDecode(int b, int& ib, int& jb) {
    int i = (int)floorf((sqrtf(8.0f * (float)b + 1.0f) - 1.0f) * 0.5f);
    while ((i + 1) * (i + 2) / 2 <= b) i++;
    while (i * (i + 1) / 2 > b) i--;
    ib = i;
    jb = b - i * (i + 1) / 2;
}
__device__ __forceinline__ int bswz(int lane, int grp) { return lane ^ (((grp >> 2) & 7) << 1); }

// ---------------- staging: gmem -> regs -> packed smem ----------------
// load a [128 x 32] row-major tile (A or n-major B): 16 floats/thread
__device__ __forceinline__ void ldT(const float* __restrict__ src, int ld, int row0, int k0,
                                    float4* p, int tid) {
#pragma unroll
    for (int it = 0; it < 4; it++) {
        int idx = tid + it * 256;
        p[it] = *(const float4*)(src + (size_t)(row0 + (idx >> 3)) * ld + k0 + (idx & 7) * 4);
    }
}
template <bool THREE>
__device__ __forceinline__ void stA(unsigned* S, const float4* pa, int tid) {
    unsigned* Ah = S;
    unsigned* Al = S + A_WORDS;
#pragma unroll
    for (int it = 0; it < 4; it++) {
        int idx = tid + it * 256;
        int r = idx >> 3, c = (idx & 7) * 4;
        int mt = r >> 4, rr = r & 15, ks = c >> 3;
        int jj = (((c & 7) >= 4) ? 2 : 0) + ((rr >= 8) ? 1 : 0);
        int base = (mt * 4 + ks) * A_GRP + ((rr & 7) << 4) + jj;
        const float* v = (const float*)&pa[it];
#pragma unroll
        for (int q = 0; q < 4; q++) {
            if (THREE) {
                unsigned h, l;
                tfsplit(v[q], h, l);
                Ah[base + q * 4] = h;
                Al[base + q * 4] = l;
            } else {
                Ah[base + q * 4] = f2tf(v[q]);
            }
        }
    }
}
template <bool THREE>
__device__ __forceinline__ void stBn(unsigned* S, const float4* pb, int tid) {
    unsigned* Bh = S + (THREE ? 2 * A_WORDS : A_WORDS);
    unsigned* Bl = Bh + B_WORDS;
#pragma unroll
    for (int it = 0; it < 4; it++) {
        int idx = tid + it * 256;
        int n = idx >> 3, c = (idx & 7) * 4;
        int nt = n >> 3, nn = n & 7, ks = c >> 3;
        int jj = ((c & 7) >= 4) ? 1 : 0;
        int grp = nt * 4 + ks;
        const float* v = (const float*)&pb[it];
#pragma unroll
        for (int q = 0; q < 4; q++) {
            int word = grp * B_GRP + (bswz(nn * 4 + q, grp) << 1) + jj;
            if (THREE) {
                unsigned h, l;
                tfsplit(v[q], h, l);
                Bh[word] = h;
                Bl[word] = l;
            } else {
                Bh[word] = f2tf(v[q]);
            }
        }
    }
}
// transposed B read for alpha @ h: B[n][k] = g_h[k0+k][colB+n]
__device__ __forceinline__ void ldBk(int k0, int colB, float4* pb, int tid) {
#pragma unroll
    for (int it = 0; it < 4; it++) {
        int idx = tid + it * 256;
        pb[it] = *(const float4*)(g_h + (size_t)(k0 + (idx >> 5)) * DD + colB + (idx & 31) * 4);
    }
}
__device__ __forceinline__ void stBk(unsigned* S, const float4* pb, int tid) {
    unsigned* Bh = S + 2 * A_WORDS;
    unsigned* Bl = Bh + B_WORDS;
#pragma unroll
    for (int it = 0; it < 4; it++) {
        int idx = tid + it * 256;
        int k = idx >> 5, n0 = (idx & 31) * 4;
        int ks = k >> 3, kk = k & 7;
        int jj = (kk >= 4) ? 1 : 0;
        int grp = (n0 >> 3) * 4 + ks;
        const float* v = (const float*)&pb[it];
#pragma unroll
        for (int q = 0; q < 4; q++) {
            int lane = ((n0 + q) & 7) * 4 + (kk & 3);
            int word = grp * B_GRP + (bswz(lane, grp) << 1) + jj;
            unsigned h, l;
            tfsplit(v[q], h, l);
            Bh[word] = h;
            Bl[word] = l;
        }
    }
}

// ---------------- MMA over one staged 32-wide K chunk ----------------------
template <bool THREE>
__device__ __forceinline__ void mma_body(const unsigned* S, float acc[4][4][4],
                                         int wm, int wn, int lane) {
    const unsigned* Ah = S;
    const unsigned* Al = S + A_WORDS;
    const unsigned* Bh = S + (THREE ? 2 * A_WORDS : A_WORDS);
    const unsigned* Bl = Bh + B_WORDS;
#pragma unroll
    for (int ks = 0; ks < 4; ks++) {
        unsigned bh[4][2], bl[4][2];
#pragma unroll
        for (int j = 0; j < 4; j++) {
            int grp = (wn * 4 + j) * 4 + ks;
            int off = grp * B_GRP + (bswz(lane, grp) << 1);
            *(uint2*)bh[j] = *(const uint2*)&Bh[off];
            if (THREE) *(uint2*)bl[j] = *(const uint2*)&Bl[off];
        }
#pragma unroll
        for (int i = 0; i < 4; i++) {
            int offA = ((wm * 4 + i) * 4 + ks) * A_GRP + lane * 4;
            unsigned ah[4], al[4];
            *(uint4*)ah = *(const uint4*)&Ah[offA];
            if (THREE) *(uint4*)al = *(const uint4*)&Al[offA];
#pragma unroll
            for (int j = 0; j < 4; j++) {
                if (THREE) {
                    mma8(acc[i][j], ah, bl[j]);
                    mma8(acc[i][j], al, bh[j]);
                }
                mma8(acc[i][j], ah, bh[j]);
            }
        }
    }
}

#define ACC_INIT(acc)                      \
    _Pragma("unroll")                      \
    for (int i = 0; i < 4; i++)            \
    _Pragma("unroll")                      \
    for (int j = 0; j < 4; j++)            \
    _Pragma("unroll")                      \
    for (int e = 0; e < 4; e++) acc[i][j][e] = 0.f;

// ---------------- kernel 1: normalize rows ----------------
__global__ void k_normalize(const float* __restrict__ x) {
    __shared__ float sh[32];
    int t = blockIdx.x;
    const float* row = x + (size_t)t * DD;
    float ss = 0.f;
    for (int i = threadIdx.x; i < DD; i += blockDim.x) {
        float v = row[i];
        ss += v * v;
    }
    ss = blockReduceSum(ss, sh);
    float inv = 1.0f / fmaxf(sqrtf(ss), 1e-12f);
    float* hr = g_h + (size_t)t * DD;
    for (int i = threadIdx.x; i < DD; i += blockDim.x)
        hr[i] = row[i] * inv;
    if (threadIdx.x == 0) {
        g_hn2[t] = ss * inv * inv;
        g_maxQ[t] = -3.0e38f;
    }
}

__global__ void k_tables() {
    int i = blockIdx.x * 256 + threadIdx.x;
    if (i < TT)
        g_invden[i] = 1.0f / (sqrtf((float)DD) * expf(0.1f * (float)i) + 1e-8f);
}

// ---------------- kernel 2: sim = h h^T (1xTF32; errors /30 by denom) ------
__global__ void __launch_bounds__(256, 1) k_sim() {
    extern __shared__ unsigned dsm[];
    int tid = threadIdx.x, lane = tid & 31, warp = tid >> 5;
    int wm = warp >> 2, wn = warp & 3, gr = lane >> 2, gc = lane & 3;
    int ib, jb;
    triDecode(blockIdx.x, ib, jb);
    int rowA = ib * BM, rowB = jb * BN;

    float acc[4][4][4];
    ACC_INIT(acc)

    float4 pa[4], pb[4];
    ldT(g_h, DD, rowA, 0, pa, tid);
    ldT(g_h, DD, rowB, 0, pb, tid);
    stA<false>(dsm, pa, tid);
    stBn<false>(dsm, pb, tid);
    ldT(g_h, DD, rowA, BK, pa, tid);
    ldT(g_h, DD, rowB, BK, pb, tid);
    __syncthreads();

    for (int kt = 0; kt < NKT_FULL; kt++) {
        if (kt + 1 < NKT_FULL) {
            unsigned* nxt = dsm + ((kt + 1) & 1) * STAGE1;
            stA<false>(nxt, pa, tid);
            stBn<false>(nxt, pb, tid);
        }
        if (kt + 2 < NKT_FULL) {
            ldT(g_h, DD, rowA, (kt + 2) * BK, pa, tid);
            ldT(g_h, DD, rowB, (kt + 2) * BK, pb, tid);
        }
        mma_body<false>(dsm + (kt & 1) * STAGE1, acc, wm, wn, lane);
        __syncthreads();
    }

#pragma unroll
    for (int i = 0; i < 4; i++) {
        int t = rowA + (wm * 4 + i) * 16 + gr;
#pragma unroll
        for (int j = 0; j < 4; j++) {
            int s = rowB + (wn * 4 + j) * 8 + gc * 2;
            *(float2*)&g_sim[(size_t)t * TT + s]       = make_float2(acc[i][j][0], acc[i][j][1]);
            *(float2*)&g_sim[(size_t)(t + 8) * TT + s] = make_float2(acc[i][j][2], acc[i][j][3]);
        }
    }
}

// ---------------- kernel 3: causal decayed softmax -------------------------
__global__ void k_softmax() {
    __shared__ float sh[32];
    int t = blockIdx.x;
    float* row = g_sim + (size_t)t * TT;
    int n = t + 1;
    float lmax = -3.0e38f;
    for (int s = threadIdx.x; s < n; s += blockDim.x) {
        float l = row[s] * g_invden[t - s];
        row[s] = l;
        lmax = fmaxf(lmax, l);
    }
    lmax = blockReduceMax(lmax, sh);
    float lsum = 0.f;
    for (int s = threadIdx.x; s < n; s += blockDim.x) {
        float e = __expf(row[s] - lmax);
        row[s] = e;
        lsum += e;
    }
    lsum = blockReduceSum(lsum, sh);
    float inv = 1.0f / lsum;
    for (int s = threadIdx.x; s < n; s += blockDim.x) row[s] *= inv;
    int zend = ((t >> 7) + 1) * 128;
    for (int s = n + threadIdx.x; s < zend; s += blockDim.x) row[s] = 0.f;
}

// ---------------- kernel 4: g = alpha @ h (3xTF32, causal K-trunc) ---------
__global__ void __launch_bounds__(256, 1) k_g() {
    extern __shared__ unsigned dsm[];
    int tid = threadIdx.x, lane = tid & 31, warp = tid >> 5;
    int wm = warp >> 2, wn = warp & 3, gr = lane >> 2, gc = lane & 3;
    int jbD = blockIdx.x, ib = blockIdx.y;
    int rowA = ib * BM, colB = jbD * BN;
    int nkt = (ib + 1) * 4;

    float acc[4][4][4];
    ACC_INIT(acc)

    float4 pa[4], pb[4];
    ldT(g_sim, TT, rowA, 0, pa, tid);
    ldBk(0, colB, pb, tid);
    stA<true>(dsm, pa, tid);
    stBk(dsm, pb, tid);
    ldT(g_sim, TT, rowA, BK, pa, tid);
    ldBk(BK, colB, pb, tid);
    __syncthreads();

    for (int kt = 0; kt < nkt; kt++) {
        if (kt + 1 < nkt) {
            unsigned* nxt = dsm + ((kt + 1) & 1) * STAGE3;
            stA<true>(nxt, pa, tid);
            stBk(nxt, pb, tid);
        }
        if (kt + 2 < nkt) {
            ldT(g_sim, TT, rowA, (kt + 2) * BK, pa, tid);
            ldBk((kt + 2) * BK, colB, pb, tid);
        }
        mma_body<true>(dsm + (kt & 1) * STAGE3, acc, wm, wn, lane);
        __syncthreads();
    }

#pragma unroll
    for (int i = 0; i < 4; i++) {
        int t = rowA + (wm * 4 + i) * 16 + gr;
#pragma unroll
        for (int j = 0; j < 4; j++) {
            int d = colB + (wn * 4 + j) * 8 + gc * 2;
            *(float2*)&g_g[(size_t)t * DD + d]       = make_float2(acc[i][j][0], acc[i][j][1]);
            *(float2*)&g_g[(size_t)(t + 8) * DD + d] = make_float2(acc[i][j][2], acc[i][j][3]);
        }
    }
}

// ---------------- kernel 5: cross = g h^T + fused causal max (3xTF32) ------
__global__ void __launch_bounds__(256, 1) k_cross() {
    extern __shared__ unsigned dsm[];
    int tid = threadIdx.x, lane = tid & 31, warp = tid >> 5;
    int wm = warp >> 2, wn = warp & 3, gr = lane >> 2, gc = lane & 3;
    int ib, jb;
    triDecode(blockIdx.x, ib, jb);
    int rowA = ib * BM, rowB = jb * BN;

    float acc[4][4][4];
    ACC_INIT(acc)

    float4 pa[4], pb[4];
    ldT(g_g, DD, rowA, 0, pa, tid);
    ldT(g_h, DD, rowB, 0, pb, tid);
    stA<true>(dsm, pa, tid);
    stBn<true>(dsm, pb, tid);
    ldT(g_g, DD, rowA, BK, pa, tid);
    ldT(g_h, DD, rowB, BK, pb, tid);
    __syncthreads();

    for (int kt = 0; kt < NKT_FULL; kt++) {
        if (kt + 1 < NKT_FULL) {
            unsigned* nxt = dsm + ((kt + 1) & 1) * STAGE3;
            stA<true>(nxt, pa, tid);
            stBn<true>(nxt, pb, tid);
        }
        if (kt + 2 < NKT_FULL) {
            ldT(g_g, DD, rowA, (kt + 2) * BK, pa, tid);
            ldT(g_h, DD, rowB, (kt + 2) * BK, pb, tid);
        }
        mma_body<true>(dsm + (kt & 1) * STAGE3, acc, wm, wn, lane);
        __syncthreads();
    }

    // epilogue: maxQ[t] = max_{s<=t}(hn2[s] - 2*cross[t,s])
    float hn[4][2];
#pragma unroll
    for (int j = 0; j < 4; j++)
#pragma unroll
        for (int e = 0; e < 2; e++)
            hn[j][e] = g_hn2[rowB + (wn * 4 + j) * 8 + gc * 2 + e];

    float* red = (float*)dsm;  // safe: all MMA reads completed (post-loop sync)
#pragma unroll
    for (int i = 0; i < 4; i++) {
        int rloc = (wm * 4 + i) * 16 + gr;
        int t0 = rowA + rloc;
        float m0 = -3.0e38f, m1 = -3.0e38f;
#pragma unroll
        for (int j = 0; j < 4; j++)
#pragma unroll
            for (int e = 0; e < 2; e++) {
                int s = rowB + (wn * 4 + j) * 8 + gc * 2 + e;
                float q0 = hn[j][e] - 2.0f * acc[i][j][e];
                float q1 = hn[j][e] - 2.0f * acc[i][j][2 + e];
                if (s <= t0)     m0 = fmaxf(m0, q0);
                if (s <= t0 + 8) m1 = fmaxf(m1, q1);
            }
#pragma unroll
        for (int o = 1; o < 4; o <<= 1) {
            m0 = fmaxf(m0, __shfl_xor_sync(0xffffffffu, m0, o));
            m1 = fmaxf(m1, __shfl_xor_sync(0xffffffffu, m1, o));
        }
        if (gc == 0) {
            red[rloc * 4 + wn]       = m0;
            red[(rloc + 8) * 4 + wn] = m1;
        }
    }
    __syncthreads();
    if (tid < 128) {
        float m = fmaxf(fmaxf(red[tid * 4], red[tid * 4 + 1]),
                        fmaxf(red[tid * 4 + 2], red[tid * 4 + 3]));
        if (m > -2.0e38f) atomicMaxF(&g_maxQ[rowA + tid], m);
    }
}

// ---------------- kernel 6: final elementwise ------------------------------
__global__ void k_final(const float* __restrict__ m_t, const float* __restrict__ c_t,
                        const float* __restrict__ d_t, const float* __restrict__ mu,
                        float* __restrict__ out) {
    __shared__ float sh[32];
    int t = blockIdx.x;
    const float* hr = g_h + (size_t)t * DD;
    const float* gr = g_g + (size_t)t * DD;
    float dd = 0.f, gn2 = 0.f;
    for (int i = threadIdx.x; i < DD; i += blockDim.x) {
        float hv = hr[i], gv = gr[i];
        float df = hv - gv;
        dd += df * df;
        gn2 += gv * gv;
    }
    dd = blockReduceSum(dd, sh);
    gn2 = blockReduceSum(gn2, sh);
    if (threadIdx.x == 0) {
        float dist = sqrtf(fmaxf(dd, 1e-24f));
        float dmax = sqrtf(fmaxf(gn2 + g_maxQ[t], 1e-24f));
        if (dmax < 1e-6f) dmax = 1.0f;
        float ratio = dist / (dmax + 1e-8f);
        float stab = 1.0f - 0.3f * c_t[t] + 0.2f * d_t[t];
        float xi = 1.0f - mu[0] * m_t[t];
        float v = ratio * stab * xi;
        out[t] = fminf(fmaxf(v, 0.0f), 1.0f);
    }
}

// ---------------- launch ----------------------------------------------------
extern "C" void kernel_launch(void* const* d_in, const int* in_sizes, int n_in,
                              void* d_out, int out_size) {
    const float* x   = (const float*)d_in[0];
    const float* m_t = (const float*)d_in[1];
    const float* c_t = (const float*)d_in[2];
    const float* d_t = (const float*)d_in[3];
    const float* mu  = (const float*)d_in[4];
    float* out = (float*)d_out;

    cudaFuncSetAttribute(k_sim,   cudaFuncAttributeMaxDynamicSharedMemorySize, DSMEM1);
    cudaFuncSetAttribute(k_g,     cudaFuncAttributeMaxDynamicSharedMemorySize, DSMEM3);
    cudaFuncSetAttribute(k_cross, cudaFuncAttributeMaxDynamicSharedMemorySize, DSMEM3);

    k_normalize<<<TT, 256>>>(x);
    k_tables<<<TT / 256, 256>>>();
    k_sim<<<NPAIR, 256, DSMEM1>>>();
    k_softmax<<<TT, 256>>>();
    k_g<<<dim3(DD / BN, NBLK), 256, DSMEM3>>>();
    k_cross<<<NPAIR, 256, DSMEM3>>>();
    k_final<<<TT, 256>>>(m_t, c_t, d_t, mu, out);
}